// round 13
// baseline (speedup 1.0000x reference)
#include <cuda_runtime.h>

#define VV   128
#define HH   512
#define BB   8192
#define OUTW 256   // 2*V

#define VG    8            // v's per GEMM block
#define KT    16           // k's per GEMM block (front-batched into regs)
#define KS2   (HH / KT)    // 32 k-segments
#define VGN2  (VV / VG)    // 16 v-groups

// Scratch (alloc-free rule: __device__ globals). g_vgdone is monotonic
// (KS2 increments per vgroup per replay) -> CUDA-graph replay safe.
__device__ float    g_part[KS2 * VV * OUTW];   // 4 MB partial sums
__device__ int      g_loc[VV];
__device__ int      g_scale[VV];
__device__ int      g_idx[BB];                 // packed (i0 | i1<<8) per row
__device__ unsigned g_vgdone[VGN2];

// Monotone orderable key for float argmax with first-index tie-break.
__device__ __forceinline__ unsigned long long amax_key(float f, int col)
{
    unsigned int u = __float_as_uint(f);
    u = (u & 0x80000000u) ? ~u : (u | 0x80000000u);
    return ((unsigned long long)u << 32) | (unsigned long long)(127 - col);
}

// ---------------------------------------------------------------------------
// Table kernel: 512 blocks = 16 vgroups x 32 ksegs, 256 threads.
// Thread = column c. ALL 16 W2 loads are issued into a register array BEFORE
// any FMA (explicit MLP=16 — R12's serial-load chain was the bottleneck).
// The KS2-th arriving block of each vgroup reduces partials + argmaxes.
// ---------------------------------------------------------------------------
__global__ void __launch_bounds__(256)
table_kernel(const float* __restrict__ W1, const float* __restrict__ b1,
             const float* __restrict__ W2, const float* __restrict__ b2)
{
    const int blk = blockIdx.x;
    const int vg = blk & (VGN2 - 1);   // 0..15
    const int ks = blk >> 4;           // 0..31
    const int v0 = vg * VG;
    const int k0 = ks * KT;
    const int t = threadIdx.x;
    const int wid = t >> 5, lane = t & 31;
    const int c = t;

    __shared__ __align__(16) float h[KT][VG];    // 512 B
    __shared__ unsigned long long skey[VG * 2];
    __shared__ int s_last;

    // h[k][v] = relu(W1[v0+v][k0+k] + b1[k0+k]); 128 entries, coalesced in k.
    if (t < KT * VG) {
        const int v = t >> 4, k = t & (KT - 1);
        h[k][v] = fmaxf(W1[(size_t)(v0 + v) * HH + k0 + k] + b1[k0 + k], 0.0f);
    }
    __syncthreads();

    // ---- front-batch ALL W2 loads (16 independent LDG.32, one exposure) ----
    const float* __restrict__ w2c = W2 + (size_t)k0 * OUTW + c;
    float w[KT];
    #pragma unroll
    for (int k = 0; k < KT; ++k)
        w[k] = w2c[(size_t)k * OUTW];             // coalesced across threads

    float acc[VG];
    #pragma unroll
    for (int v = 0; v < VG; ++v) acc[v] = 0.0f;

    #pragma unroll
    for (int k = 0; k < KT; ++k) {
        const float4 h03 = *reinterpret_cast<const float4*>(&h[k][0]);
        const float4 h47 = *reinterpret_cast<const float4*>(&h[k][4]);
        acc[0] = fmaf(h03.x, w[k], acc[0]);
        acc[1] = fmaf(h03.y, w[k], acc[1]);
        acc[2] = fmaf(h03.z, w[k], acc[2]);
        acc[3] = fmaf(h03.w, w[k], acc[3]);
        acc[4] = fmaf(h47.x, w[k], acc[4]);
        acc[5] = fmaf(h47.y, w[k], acc[5]);
        acc[6] = fmaf(h47.z, w[k], acc[6]);
        acc[7] = fmaf(h47.w, w[k], acc[7]);
    }

    #pragma unroll
    for (int v = 0; v < VG; ++v)                  // coalesced per v
        g_part[((size_t)ks * VV + v0 + v) * OUTW + c] = acc[v];

    // ---- vgroup completion: last arriver reduces + argmaxes its 8 v's -----
    if (t == 0) {
        __threadfence();                          // release partials
        const unsigned my = atomicAdd(&g_vgdone[vg], 1u);
        s_last = ((my & (KS2 - 1u)) == (KS2 - 1u));
    }
    if (t < VG * 2) skey[t] = 0ULL;
    __syncthreads();

    if (s_last) {
        const float bb = b2[c];
        const int half = c >> 7;                  // uniform within each warp
        const int col = c & 127;

        #pragma unroll
        for (int v = 0; v < VG; ++v) {
            // hand-batched: 32 independent loads into a temp array, then sum
            float ps[KS2];
            #pragma unroll
            for (int s8 = 0; s8 < KS2; ++s8)
                ps[s8] = g_part[((size_t)s8 * VV + v0 + v) * OUTW + c];
            float sum = bb;
            #pragma unroll
            for (int s8 = 0; s8 < KS2; ++s8) sum += ps[s8];

            // warp pre-reduce (32 cols, same half), then 1 atomic per warp
            unsigned long long key = amax_key(sum, col);
            #pragma unroll
            for (int off = 16; off > 0; off >>= 1) {
                const unsigned long long o = __shfl_xor_sync(0xFFFFFFFFu, key, off);
                if (o > key) key = o;
            }
            if (lane == 0) atomicMax(&skey[v * 2 + half], key);
        }
        __syncthreads();

        if (t < VG) {
            g_loc[v0 + t]   = 127 - (int)(skey[t * 2]     & 0xFFFFFFFFULL);
            g_scale[v0 + t] = 127 - (int)(skey[t * 2 + 1] & 0xFFFFFFFFULL);
        }
    }
}

// ---------------------------------------------------------------------------
// Copy kernel: 256 blocks x 256 thr, 8 warps x 4 rows = 32 rows/block.
// Front-batched loads (MLP 8). Copy x0 -> out[:128], zero out[128:],
// extract (i0,i1) -> g_idx. x0/x1 are EXACT one-hots.
// ---------------------------------------------------------------------------
__global__ void __launch_bounds__(256)
copy_kernel(const float* __restrict__ in, float* __restrict__ out)
{
    const int t = threadIdx.x;
    const int wid = t >> 5, lane = t & 31;
    const int r0 = blockIdx.x * 32 + wid * 4;

    const float4* in4 = reinterpret_cast<const float4*>(in);
    float4* out4 = reinterpret_cast<float4*>(out);

    float4 a[4], c4[4];
    #pragma unroll
    for (int i = 0; i < 4; ++i) {       // front-batched: MLP 8
        const size_t base = (size_t)(r0 + i) * 64;
        a[i] = in4[base + lane];
        c4[i] = in4[base + 32 + lane];
    }

    const float4 z4 = make_float4(0.f, 0.f, 0.f, 0.f);
    #pragma unroll
    for (int i = 0; i < 4; ++i) {
        const int m0 = (a[i].x == 1.0f) | ((a[i].y == 1.0f) << 1) |
                       ((a[i].z == 1.0f) << 2) | ((a[i].w == 1.0f) << 3);
        const int m1 = (c4[i].x == 1.0f) | ((c4[i].y == 1.0f) << 1) |
                       ((c4[i].z == 1.0f) << 2) | ((c4[i].w == 1.0f) << 3);

        // one-hot -> index = sum of the single nonzero lane contribution
        const int li0 = m0 ? (lane * 4 + __ffs(m0) - 1) : 0;
        const int li1 = m1 ? (lane * 4 + __ffs(m1) - 1) : 0;
        const int i0 = __reduce_add_sync(0xFFFFFFFFu, li0);
        const int i1 = __reduce_add_sync(0xFFFFFFFFu, li1);

        const size_t base = (size_t)(r0 + i) * 64;
        out4[base + lane] = a[i];
        out4[base + 32 + lane] = z4;
        if (lane == 0) g_idx[r0 + i] = i0 | (i1 << 8);
    }
}

// ---------------------------------------------------------------------------
// Scatter kernel: 1 thread per row; single conditional 4-byte store into the
// already-zeroed second half. Runs after BOTH branches (graph join).
// ---------------------------------------------------------------------------
__global__ void __launch_bounds__(256)
scatter_kernel(float* __restrict__ out)
{
    const int row = blockIdx.x * 256 + threadIdx.x;
    const int pk = g_idx[row];
    const int i0 = pk & 255;
    const int i1 = pk >> 8;
    const int l = g_loc[i0];
    const int s = g_scale[i0];
    if (s != 0) {
        const int tcol = (l + i1 * s) & (VV - 1);
        out[(size_t)row * OUTW + VV + tcol] = 1.0f;
    }
}

// ---------------------------------------------------------------------------
// Launch: forked-graph schedule (verified to overlap in R12). Streams/events
// created once on the first (uncaptured correctness) call; captured work is
// identical every call. Inputs: inputs, W1, b1, W2, b2.
// ---------------------------------------------------------------------------
extern "C" void kernel_launch(void* const* d_in, const int* in_sizes, int n_in,
                              void* d_out, int out_size)
{
    const float* in = (const float*)d_in[0];
    const float* W1 = (const float*)d_in[1];
    const float* b1 = (const float*)d_in[2];
    const float* W2 = (const float*)d_in[3];
    const float* b2 = (const float*)d_in[4];
    float* out = (float*)d_out;

    static cudaStream_t s2 = nullptr;
    static cudaEvent_t evRoot = nullptr, evTab = nullptr;
    if (s2 == nullptr) {
        cudaStreamCreateWithFlags(&s2, cudaStreamNonBlocking);
        cudaEventCreateWithFlags(&evRoot, cudaEventDisableTiming);
        cudaEventCreateWithFlags(&evTab, cudaEventDisableTiming);
    }

    // Fork: s2 joins the capture via the root event.
    cudaEventRecord(evRoot, 0);
    cudaStreamWaitEvent(s2, evRoot, 0);

    // Branch 1 (s2): tables.
    table_kernel<<<VGN2 * KS2, 256, 0, s2>>>(W1, b1, W2, b2);
    cudaEventRecord(evTab, s2);

    // Branch 2 (main): bulk copy/zero/extract — independent of tables.
    copy_kernel<<<BB / 32, 256>>>(in, out);

    // Join: scatter needs tables + copy.
    cudaStreamWaitEvent(0, evTab, 0);
    scatter_kernel<<<BB / 256, 256>>>(out);
}

// round 14
// speedup vs baseline: 1.2505x; 1.2505x over previous
#include <cuda_runtime.h>

#define VV   128
#define HH   512
#define BB   8192
#define OUTW 256   // 2*V

#define VG    8            // v's per GEMM block
#define KT    32           // k's per GEMM block
#define KS2   (HH / KT)    // 16 k-segments
#define VGN2  (VV / VG)    // 16 v-groups
#define NGEMM 256          // 16 vg x 16 ks
#define NCOPY 256          // 32 rows each
#define NBLK  (NGEMM + NCOPY)
#define THR   256

// Scratch (alloc-free rule: __device__ globals). All counters monotonic
// (never reset) -> CUDA-graph replay safe.
__device__ float    g_part[KS2 * VV * OUTW];   // 2 MB partial sums
__device__ int      g_loc[VV];
__device__ int      g_scale[VV];
__device__ unsigned g_vgdone[VGN2];            // 16 increments per vg/replay
__device__ unsigned g_ready = 0u;              // 16 increments per replay
__device__ unsigned g_copy_epoch = 0u;         // 256 increments per replay

// Monotone orderable key for float argmax with first-index tie-break.
__device__ __forceinline__ unsigned long long amax_key(float f, int col)
{
    unsigned int u = __float_as_uint(f);
    u = (u & 0x80000000u) ? ~u : (u | 0x80000000u);
    return ((unsigned long long)u << 32) | (unsigned long long)(127 - col);
}

__device__ __forceinline__ void cp_async16(void* smem_dst, const void* gmem_src)
{
    unsigned long long sa = __cvta_generic_to_shared(smem_dst);
    asm volatile("cp.async.cg.shared.global [%0], [%1], 16;\n"
                 :: "r"((unsigned)sa), "l"(gmem_src) : "memory");
}

__global__ void __launch_bounds__(THR)
fused_kernel(const float* __restrict__ in, const float* __restrict__ W1,
             const float* __restrict__ b1, const float* __restrict__ W2,
             const float* __restrict__ b2, float* __restrict__ out)
{
    const int blk = blockIdx.x;
    const int t = threadIdx.x;
    const int wid = t >> 5, lane = t & 31;

    __shared__ __align__(16) float smW2[KT][OUTW];   // 32 KB (GEMM only)
    __shared__ __align__(16) float h[KT][VG];        // 1 KB
    __shared__ unsigned long long skey[VG * 2];
    __shared__ int s_last;
    __shared__ unsigned s_target;
    __shared__ int sIdx[32];

    if (blk < NGEMM) {
        // ================= GEMM duty ========================================
        const int vg = blk & (VGN2 - 1);   // 0..15
        const int ks = blk >> 4;           // 0..15
        const int v0 = vg * VG;
        const int k0 = ks * KT;
        const int c = t;

        // Stage the W2 tile [k0, k0+32) x 256 cols into smem via cp.async:
        // 2048 float4, 8 per thread, hardware-pipelined (MLP=8, zero regs).
        {
            const float4* __restrict__ g4 =
                reinterpret_cast<const float4*>(W2 + (size_t)k0 * OUTW);
            float4* s4 = reinterpret_cast<float4*>(&smW2[0][0]);
            #pragma unroll
            for (int i = 0; i < 8; ++i)
                cp_async16(&s4[t + i * THR], &g4[t + i * THR]);
            asm volatile("cp.async.commit_group;\n" ::: "memory");
        }

        // h[k][v] = relu(W1[v0+v][k0+k] + b1[k0+k]); 256 entries, 1/thread.
        {
            const int v = t >> 5, k = t & (KT - 1);
            h[k][v] = fmaxf(W1[(size_t)(v0 + v) * HH + k0 + k] + b1[k0 + k], 0.0f);
        }
        if (t < VG * 2) skey[t] = 0ULL;

        asm volatile("cp.async.wait_group 0;\n" ::: "memory");
        __syncthreads();

        // Thread-per-column accumulate from SMEM (29-cyc lat, not 250).
        float acc[VG];
        #pragma unroll
        for (int v = 0; v < VG; ++v) acc[v] = 0.0f;

        #pragma unroll 4
        for (int k = 0; k < KT; ++k) {
            const float w = smW2[k][c];                       // conflict-free LDS
            const float4 h03 = *reinterpret_cast<const float4*>(&h[k][0]);
            const float4 h47 = *reinterpret_cast<const float4*>(&h[k][4]);
            acc[0] = fmaf(h03.x, w, acc[0]);
            acc[1] = fmaf(h03.y, w, acc[1]);
            acc[2] = fmaf(h03.z, w, acc[2]);
            acc[3] = fmaf(h03.w, w, acc[3]);
            acc[4] = fmaf(h47.x, w, acc[4]);
            acc[5] = fmaf(h47.y, w, acc[5]);
            acc[6] = fmaf(h47.z, w, acc[6]);
            acc[7] = fmaf(h47.w, w, acc[7]);
        }

        #pragma unroll
        for (int v = 0; v < VG; ++v)                          // coalesced per v
            g_part[((size_t)ks * VV + v0 + v) * OUTW + c] = acc[v];

        // ---- vgroup completion: 16th arriver reduces + argmaxes its 8 v's --
        if (t == 0) {
            __threadfence();                                  // release partials
            const unsigned my = atomicAdd(&g_vgdone[vg], 1u);
            s_last = ((my & (KS2 - 1u)) == (KS2 - 1u));
        }
        __syncthreads();

        if (s_last) {
            const float bb = b2[c];
            const int half = c >> 7;                          // warp-uniform
            const int col = c & 127;

            #pragma unroll
            for (int v = 0; v < VG; ++v) {
                float ps[KS2];
                #pragma unroll
                for (int s8 = 0; s8 < KS2; ++s8)
                    ps[s8] = g_part[((size_t)s8 * VV + v0 + v) * OUTW + c];
                float sum = bb;
                #pragma unroll
                for (int s8 = 0; s8 < KS2; ++s8) sum += ps[s8];

                unsigned long long key = amax_key(sum, col);
                #pragma unroll
                for (int off = 16; off > 0; off >>= 1) {
                    const unsigned long long o =
                        __shfl_xor_sync(0xFFFFFFFFu, key, off);
                    if (o > key) key = o;
                }
                if (lane == 0) atomicMax(&skey[v * 2 + half], key);
            }
            __syncthreads();

            if (t < VG) {
                g_loc[v0 + t]   = 127 - (int)(skey[t * 2]     & 0xFFFFFFFFULL);
                g_scale[v0 + t] = 127 - (int)(skey[t * 2 + 1] & 0xFFFFFFFFULL);
            }
            __syncthreads();
            if (t == 0) {
                __threadfence();                              // release tables
                atomicAdd(&g_ready, 1u);
            }
        }
    } else {
        // ================= Copy duty: 32 rows ===============================
        const int rb = blk - NGEMM;

        // Replay-safe epoch target: tickets of replay r are [256r, 256r+256)
        // -> need g_ready >= 16*(r+1).
        if (t == 0) {
            const unsigned my = atomicAdd(&g_copy_epoch, 1u);
            s_target = ((my >> 8) + 1u) * 16u;
        }

        const int r0 = rb * 32 + wid * 4;   // 8 warps x 4 rows
        const float4* in4 = reinterpret_cast<const float4*>(in);
        float4* out4 = reinterpret_cast<float4*>(out);

        float4 a[4], c4[4];
        #pragma unroll
        for (int i = 0; i < 4; ++i) {       // front-batched: MLP 8
            const size_t base = (size_t)(r0 + i) * 64;
            a[i] = in4[base + lane];
            c4[i] = in4[base + 32 + lane];
        }

        const float4 z4 = make_float4(0.f, 0.f, 0.f, 0.f);
        #pragma unroll
        for (int i = 0; i < 4; ++i) {
            const int m0 = (a[i].x == 1.0f) | ((a[i].y == 1.0f) << 1) |
                           ((a[i].z == 1.0f) << 2) | ((a[i].w == 1.0f) << 3);
            const int m1 = (c4[i].x == 1.0f) | ((c4[i].y == 1.0f) << 1) |
                           ((c4[i].z == 1.0f) << 2) | ((c4[i].w == 1.0f) << 3);

            // one-hot -> index = sum of the single nonzero lane contribution
            const int li0 = m0 ? (lane * 4 + __ffs(m0) - 1) : 0;
            const int li1 = m1 ? (lane * 4 + __ffs(m1) - 1) : 0;
            const int i0 = __reduce_add_sync(0xFFFFFFFFu, li0);
            const int i1 = __reduce_add_sync(0xFFFFFFFFu, li1);

            const size_t base = (size_t)(r0 + i) * 64;
            out4[base + lane] = a[i];
            out4[base + 32 + lane] = z4;
            if (lane == 0) sIdx[wid * 4 + i] = i0 | (i1 << 8);
        }
        __syncthreads();

        // Wait for all 16 vgroup tables of THIS replay, then scatter our rows.
        if (t == 0) {
            while ((int)(*(volatile unsigned*)&g_ready - s_target) < 0)
                __nanosleep(64);
            __threadfence();                                  // acquire tables
        }
        __syncthreads();

        if (wid == 0) {
            const int row = rb * 32 + lane;
            const int pk = sIdx[lane];
            const int i0 = pk & 255;
            const int i1 = pk >> 8;
            const int l = g_loc[i0];
            const int s = g_scale[i0];
            if (s != 0) {
                const int tcol = (l + i1 * s) & (VV - 1);
                out[(size_t)row * OUTW + VV + tcol] = 1.0f;
            }
        }
    }
}

// ---------------------------------------------------------------------------
// Launch: single kernel; GEMM blocks first so tables finish before copy
// blocks need them. Inputs in setup_inputs() order: inputs, W1, b1, W2, b2.
// ---------------------------------------------------------------------------
extern "C" void kernel_launch(void* const* d_in, const int* in_sizes, int n_in,
                              void* d_out, int out_size)
{
    const float* in = (const float*)d_in[0];
    const float* W1 = (const float*)d_in[1];
    const float* b1 = (const float*)d_in[2];
    const float* W2 = (const float*)d_in[3];
    const float* b2 = (const float*)d_in[4];
    float* out = (float*)d_out;

    fused_kernel<<<NBLK, THR>>>(in, W1, b1, W2, b2, out);
}